// round 11
// baseline (speedup 1.0000x reference)
#include <cuda_runtime.h>

// LSTM_53815940218945: B=8192, T=256, I=1, H=50, O=1
// OCCUPANCY RESTRUCTURE: block = 400 threads, 8 batch lanes, occ 2 -> 25 warps/SM.
// Thread (q, r2, s): j = q*8 + r2*4 + s.
//   q  = cell 0..49
//   r2 = gate-pair: 0 -> gates (i,f) = rows {q, 50+q}; 1 -> (g,o) = {100+q, 150+q}
//   s  = k-split over KCH=13 (k in [13s, 13s+13))
// Each thread: 2 gate rows x 13 k packed (w,w) = 52 weight regs (half of R7).
// Per step, per lane-group g (2 groups of 4 batch lanes):
//   13 LDS.128 + 52 FFMA2 -> reduce-scatter over s (6 SHFL.32) ->
//   2 activations locally (MUFU split across the r2 pair) ->
//   one xor-4 u64 SHFL merges (i,f) with (g,o) -> r2=0 does c/h update + STS.
// h double-buffered, stride 8 (bank-conflict-free) -> ONE barrier per step.

#define T_LEN  256
#define H      50
#define KCH    13
#define KP     52
#define BT     8
#define NG     2

typedef unsigned long long u64;

__device__ __forceinline__ u64 pack2(float a, float b) {
    u64 r; asm("mov.b64 %0, {%1, %2};" : "=l"(r) : "f"(a), "f"(b)); return r;
}
__device__ __forceinline__ u64 fma2(u64 a, u64 b, u64 c) {
    u64 d; asm("fma.rn.f32x2 %0, %1, %2, %3;" : "=l"(d) : "l"(a), "l"(b), "l"(c));
    return d;
}
__device__ __forceinline__ u64 add2(u64 a, u64 b) {
    u64 d; asm("add.rn.f32x2 %0, %1, %2;" : "=l"(d) : "l"(a), "l"(b));
    return d;
}
__device__ __forceinline__ float lo_of(u64 v) {
    return __uint_as_float((unsigned)v);
}
__device__ __forceinline__ float hi_of(u64 v) {
    return __uint_as_float((unsigned)(v >> 32));
}
__device__ __forceinline__ float tanh_hw(float x) {
    float y; asm("tanh.approx.f32 %0, %1;" : "=f"(y) : "f"(x)); return y;
}
__device__ __forceinline__ float sigmoid_hw(float x) {
    return fmaf(0.5f, tanh_hw(0.5f * x), 0.5f);
}

__global__ void __launch_bounds__(400, 2) lstm_kernel(
    const float* __restrict__ x,      // [B, T, 1]
    const float* __restrict__ W_ih,   // [200, 1]
    const float* __restrict__ W_hh,   // [200, 50]
    const float* __restrict__ b_ih,   // [200]
    const float* __restrict__ b_hh,   // [200]
    const float* __restrict__ W_lin,  // [1, 50]
    const float* __restrict__ b_lin,  // [1]
    float* __restrict__ out)          // [B]
{
    __shared__ __align__(16) float x_s[T_LEN * BT];    // [t][lane]
    __shared__ __align__(16) float h2_s[2][KP * BT];   // [plane][k][lane]

    const int j    = threadIdx.x;     // 0..399
    const int q    = j >> 3;          // cell 0..49
    const int r2   = (j >> 2) & 1;    // gate pair
    const int s    = j & 3;           // k-split
    const int lane = j & 31;
    const int b0 = blockIdx.x * BT;
    const int k0 = s * KCH;

    const unsigned mask4 = 0xFu  << (lane & ~3);  // reduce-scatter group
    const unsigned mask8 = 0xFFu << (lane & ~7);  // r2 pair exchange

    // Preload x tile: x_s[t][b] = x[(b0+b)*T + t]
    for (int i = j; i < T_LEN * BT; i += 400) {
        int b = i >> 8;
        int t = i & (T_LEN - 1);
        x_s[t * BT + b] = x[(b0 + b) * T_LEN + t];
    }
    // zero both h planes incl. pad rows 50,51 (stay 0 forever)
    for (int i = j; i < KP * BT; i += 400) {
        h2_s[0][i] = 0.0f;
        h2_s[1][i] = 0.0f;
    }

    // Weights: 2 gate rows x KCH ks, packed (w,w).
    u64 W2[2][KCH];
    float bias[2], wih[2];
    #pragma unroll
    for (int r = 0; r < 2; r++) {
        int row = (r2 * 2 + r) * H + q;   // gate order i,f,g,o
        bias[r] = b_ih[row] + b_hh[row];
        wih[r]  = W_ih[row];
        #pragma unroll
        for (int i = 0; i < KCH; i++) {
            int k = k0 + i;
            float w = (k < H) ? W_hh[row * H + k] : 0.0f;
            W2[r][i] = pack2(w, w);
        }
    }
    // Activation constants for my first gate (i for r2=0: sigmoid; g for r2=1: tanh).
    // v = sc*tanh(sa*y) + of ; second gate (f / o) is always sigmoid.
    const float sa0 = r2 ? 1.0f : 0.5f;
    const float sc0 = r2 ? 1.0f : 0.5f;
    const float of0 = r2 ? 0.0f : 0.5f;

    float c_reg[NG] = {0.0f, 0.0f};   // used by r2=0 only
    const bool lowhalf = (s < 2);
    const bool oddlane = (s & 1);

    __syncthreads();

    #pragma unroll 1
    for (int t = 0; t < T_LEN; t++) {
        const int ping = t & 1;
        const float* hplane = h2_s[ping];
        float* hnext = h2_s[ping ^ 1];

        #pragma unroll
        for (int g = 0; g < NG; g++) {
            // ---- gate partials: 13 LDS.128, 52 FFMA2 ----
            u64 a[2][2];
            a[0][0] = 0ull; a[0][1] = 0ull; a[1][0] = 0ull; a[1][1] = 0ull;
            #pragma unroll
            for (int i = 0; i < KCH; i++) {
                ulonglong2 hv = *reinterpret_cast<const ulonglong2*>(
                    &hplane[(k0 + i) * BT + g * 4]);
                a[0][0] = fma2(W2[0][i], hv.x, a[0][0]);
                a[0][1] = fma2(W2[0][i], hv.y, a[0][1]);
                a[1][0] = fma2(W2[1][i], hv.x, a[1][0]);
                a[1][1] = fma2(W2[1][i], hv.y, a[1][1]);
            }

            // ---- reduce-scatter over the 4 split lanes (6 SHFL.32) ----
            float g2[2];
            #pragma unroll
            for (int r = 0; r < 2; r++) {
                u64 kv = lowhalf ? a[r][0] : a[r][1];
                u64 sv = lowhalf ? a[r][1] : a[r][0];
                u64 rv = __shfl_xor_sync(mask4, sv, 2);
                u64 keep = add2(kv, rv);
                float mine  = oddlane ? hi_of(keep) : lo_of(keep);
                float sendf = oddlane ? lo_of(keep) : hi_of(keep);
                float rf = __shfl_xor_sync(mask4, sendf, 1);
                g2[r] = mine + rf;
            }

            // ---- my 2 activations (MUFU split across the r2 pair) ----
            float xv = x_s[t * BT + g * 4 + s];
            float y0 = fmaf(wih[0], xv, g2[0] + bias[0]);
            float y1 = fmaf(wih[1], xv, g2[1] + bias[1]);
            float v0 = fmaf(sc0, tanh_hw(sa0 * y0), of0);  // i_ or g_
            float v1 = sigmoid_hw(y1);                      // f_ or o_

            // ---- merge (i,f) with (g,o): one u64 shfl across xor-4 ----
            u64 recvp = __shfl_xor_sync(mask8, pack2(v0, v1), 4);
            if (r2 == 0) {
                float i_ = v0, f_ = v1;
                float g_ = lo_of(recvp), o_ = hi_of(recvp);
                c_reg[g] = fmaf(f_, c_reg[g], i_ * g_);
                hnext[q * BT + g * 4 + s] = o_ * tanh_hw(c_reg[g]);
            }
        }
        __syncthreads();
    }

    // Final h is in plane 0 (T_LEN even). out[b] = b_lin + sum_k h[k][b]*W_lin[k]
    if (j < BT) {
        const float* hf = h2_s[0];
        float sum = b_lin[0];
        #pragma unroll
        for (int k = 0; k < H; k++)
            sum = fmaf(hf[k * BT + j], W_lin[k], sum);
        out[b0 + j] = sum;
    }
}

extern "C" void kernel_launch(void* const* d_in, const int* in_sizes, int n_in,
                              void* d_out, int out_size) {
    const float* x     = (const float*)d_in[0];
    const float* W_ih  = (const float*)d_in[1];
    const float* W_hh  = (const float*)d_in[2];
    const float* b_ih  = (const float*)d_in[3];
    const float* b_hh  = (const float*)d_in[4];
    const float* W_lin = (const float*)d_in[5];
    const float* b_lin = (const float*)d_in[6];
    float* out = (float*)d_out;

    int B = in_sizes[0] / T_LEN;   // I = 1
    int blocks = B / BT;           // 1024 for B=8192

    lstm_kernel<<<blocks, 400>>>(x, W_ih, W_hh, b_ih, b_hh, W_lin, b_lin, out);
}

// round 13
// speedup vs baseline: 2.5249x; 2.5249x over previous
#include <cuda_runtime.h>
#include <cuda_bf16.h>
#include <cstdint>

// LSTM_53815940218945 via classic tensor-core mma.sync (bf16x3 Ootomo split).
// CTA = 64 batch rows, 512 threads = 16 warps (wm 0..3 x 16 rows, wn 0..3 x 7 n8-tiles).
// Per step: gates[64,224] = A[64,64] @ B[224,64]^T, 3 passes (AhiBhi, AloBhi, AhiBlo)
// f32 accumulate. A = [h | 1 | x_t | 0], bf16 hi/lo in smem (SW128), rebuilt in-place.
// B rows n = cell*4 + gate: [W_hh[gate*50+cell,:] | bias | w_ih | 0], static hi/lo.
// n8 tile = 2 cells; accumulator layout puts (i,f)/(g,o) of a cell in xor-1 partner
// threads -> ONE u64 shfl per tile; each thread updates 7 (cell,row) pairs, c in regs.

#define T_LEN 256
#define HDIM  50
#define MB    64
#define NTHR  512
#define NTW   7      // n8 tiles per warp
#define NROWS 224    // padded B rows (56 cells)

// smem layout (bytes)
#define SM_XS  0                      // x_s[256][64] f32 = 65536
#define SM_AH  65536                  // A_hi 64*128 = 8192
#define SM_AL  (SM_AH + 8192)
#define SM_BH  (SM_AL + 8192)         // B_hi 224*128 = 28672
#define SM_BL  (SM_BH + 28672)
#define SM_RED (SM_BL + 28672)        // red[64][8] f32 = 2048
#define SM_TOT (SM_RED + 2048)        // 141312

typedef unsigned long long u64;

__device__ __forceinline__ uint32_t smem_u32(const void* p) {
    uint32_t a;
    asm("{ .reg .u64 t; cvta.to.shared.u64 t, %1; cvt.u32.u64 %0, t; }"
        : "=r"(a) : "l"(p));
    return a;
}
__device__ __forceinline__ uint32_t sw128(uint32_t b) {
    return b ^ ((b >> 3) & 0x70);
}
__device__ __forceinline__ float tanh_hw(float x) {
    float y; asm("tanh.approx.f32 %0, %1;" : "=f"(y) : "f"(x)); return y;
}
__device__ __forceinline__ float sigmoid_hw(float x) {
    return fmaf(0.5f, tanh_hw(0.5f * x), 0.5f);
}
__device__ __forceinline__ u64 pack2f(float a, float b) {
    u64 r; asm("mov.b64 %0, {%1, %2};" : "=l"(r) : "f"(a), "f"(b)); return r;
}
__device__ __forceinline__ float lo_of(u64 v) { return __uint_as_float((unsigned)v); }
__device__ __forceinline__ float hi_of(u64 v) { return __uint_as_float((unsigned)(v >> 32)); }

#define LDSM4(r0, r1, r2, r3, a) \
    asm volatile("ldmatrix.sync.aligned.m8n8.x4.shared.b16 {%0,%1,%2,%3}, [%4];" \
                 : "=r"(r0), "=r"(r1), "=r"(r2), "=r"(r3) : "r"(a))

__device__ __forceinline__ void mma_bf16(float* d, const uint32_t* a,
                                         const uint32_t* b) {
    asm volatile(
        "mma.sync.aligned.m16n8k16.row.col.f32.bf16.bf16.f32 "
        "{%0,%1,%2,%3}, {%4,%5,%6,%7}, {%8,%9}, {%0,%1,%2,%3};"
        : "+f"(d[0]), "+f"(d[1]), "+f"(d[2]), "+f"(d[3])
        : "r"(a[0]), "r"(a[1]), "r"(a[2]), "r"(a[3]), "r"(b[0]), "r"(b[1]));
}

__device__ __forceinline__ void store_bf16_split(char* smem, uint32_t off_hi_base,
                                                 uint32_t off_lo_base,
                                                 uint32_t byte_off, float v) {
    __nv_bfloat16 hi = __float2bfloat16(v);
    float lo = v - __bfloat162float(hi);
    uint32_t so = sw128(byte_off);
    *reinterpret_cast<__nv_bfloat16*>(smem + off_hi_base + so) = hi;
    *reinterpret_cast<__nv_bfloat16*>(smem + off_lo_base + so) = __float2bfloat16(lo);
}

__global__ __launch_bounds__(NTHR, 1) void lstm_mma_kernel(
    const float* __restrict__ x,      // [B, T, 1]
    const float* __restrict__ W_ih,   // [200, 1]
    const float* __restrict__ W_hh,   // [200, 50]
    const float* __restrict__ b_ih,   // [200]
    const float* __restrict__ b_hh,   // [200]
    const float* __restrict__ W_lin,  // [1, 50]
    const float* __restrict__ b_lin,  // [1]
    float* __restrict__ out)          // [B]
{
    extern __shared__ __align__(1024) char smem[];
    const uint32_t sb = smem_u32(smem);
    const int tid  = threadIdx.x;
    const int wid  = tid >> 5, lane = tid & 31;
    const int wm   = wid & 3, wn = wid >> 2;        // warp row/col in tile grid
    const int m0   = wm * 16;
    const int nt0  = wn * NTW;                      // first n8 tile
    const int b0   = blockIdx.x * MB;

    const int t3   = lane & 3;
    const int half = lane & 1;                      // 0: row g, 1: row g+8
    const int myrow = m0 + (lane >> 2) + 8 * half;  // batch row (0..63) this thread updates

    float* x_s = reinterpret_cast<float*>(smem + SM_XS);

    // ---- load x tile: x_s[t*64 + r] = x[(b0+r)*T + t] (coalesced along t)
    for (int i = tid; i < MB * T_LEN; i += NTHR) {
        int r = i >> 8, t = i & (T_LEN - 1);
        x_s[t * MB + r] = x[(size_t)(b0 + r) * T_LEN + t];
    }
    // ---- zero A tiles (h=0 & pad)
    for (int i = tid; i < (8192 * 2) / 4; i += NTHR)
        reinterpret_cast<uint32_t*>(smem + SM_AH)[i] = 0u;
    // ---- build static B tiles (hi/lo), rows n = cell*4 + gate, K-major SW128
    for (int idx = tid; idx < NROWS * 64; idx += NTHR) {
        int n = idx >> 6, k = idx & 63;
        float v = 0.0f;
        if (n < 200) {
            int cell = n >> 2, gate = n & 3;
            int wr = gate * HDIM + cell;            // PyTorch gate order i,f,g,o
            if (k < HDIM)           v = W_hh[wr * HDIM + k];
            else if (k == HDIM)     v = b_ih[wr] + b_hh[wr];
            else if (k == HDIM + 1) v = W_ih[wr];
        }
        store_bf16_split(smem, SM_BH, SM_BL, (uint32_t)(n * 128 + k * 2), v);
    }
    __syncthreads();
    // ---- ones column (k=50) and x column (k=51) for t=0
    if (tid < MB) {
        uint32_t so = sw128((uint32_t)(tid * 128 + HDIM * 2));
        *reinterpret_cast<__nv_bfloat16*>(smem + SM_AH + so) = __float2bfloat16(1.0f);
        store_bf16_split(smem, SM_AH, SM_AL,
                         (uint32_t)(tid * 128 + (HDIM + 1) * 2), x_s[tid]);
    }

    // ---- per-thread state: 7 (cell,row) pairs
    float cst[NTW], wl[NTW];
    int mycell[NTW];
    #pragma unroll
    for (int nt = 0; nt < NTW; nt++) {
        cst[nt] = 0.0f;
        int cell = (nt0 + nt) * 2 + (t3 >> 1);
        mycell[nt] = cell;
        wl[nt] = (cell < HDIM) ? W_lin[cell] : 0.0f;
    }
    float partial = 0.0f;

    // ---- ldmatrix addresses (fixed per thread)
    // A frag (m16k16, tile kt): m = m0+(lane&7)+8*((lane>>3)&1), k = kt*16+8*(lane>>4)
    const uint32_t a_m = (uint32_t)(m0 + (lane & 7) + 8 * ((lane >> 3) & 1));
    const uint32_t a_koff = (uint32_t)(8 * (lane >> 4));
    // B frag pair (n8 x k32 per LDSM4): n = nt*8+(lane&7), k = kh*32+8*(lane>>3)
    const uint32_t b_nrow = (uint32_t)((lane & 7));
    const uint32_t b_koff = (uint32_t)(8 * (lane >> 3));

    #pragma unroll 1
    for (int t = 0; t < T_LEN; t++) {
        __syncthreads();   // A (h + x col) ready for this step

        // ---- load A fragments: 4 k-tiles x (hi, lo)
        uint32_t ah[16], al[16];
        #pragma unroll
        for (int kt = 0; kt < 4; kt++) {
            uint32_t koff2 = (uint32_t)(kt * 16) + a_koff;
            uint32_t so = sw128(a_m * 128 + koff2 * 2);
            LDSM4(ah[4*kt], ah[4*kt+1], ah[4*kt+2], ah[4*kt+3], sb + SM_AH + so);
            LDSM4(al[4*kt], al[4*kt+1], al[4*kt+2], al[4*kt+3], sb + SM_AL + so);
        }

        // ---- GEMM: 7 n-tiles, 4 k-tiles, 3 passes
        float d[NTW][4];
        #pragma unroll
        for (int nt = 0; nt < NTW; nt++) {
            uint32_t n = (uint32_t)((nt0 + nt) * 8) + b_nrow;
            uint32_t bh[8], bl[8];
            {
                uint32_t so0 = sw128(n * 128 + (b_koff) * 2);
                uint32_t so1 = sw128(n * 128 + (32 + b_koff) * 2);
                LDSM4(bh[0], bh[1], bh[2], bh[3], sb + SM_BH + so0);
                LDSM4(bh[4], bh[5], bh[6], bh[7], sb + SM_BH + so1);
                LDSM4(bl[0], bl[1], bl[2], bl[3], sb + SM_BL + so0);
                LDSM4(bl[4], bl[5], bl[6], bl[7], sb + SM_BL + so1);
            }
            d[nt][0] = 0.0f; d[nt][1] = 0.0f; d[nt][2] = 0.0f; d[nt][3] = 0.0f;
            #pragma unroll
            for (int kt = 0; kt < 4; kt++)
                mma_bf16(d[nt], ah + 4 * kt, bh + 2 * kt);
            #pragma unroll
            for (int kt = 0; kt < 4; kt++)
                mma_bf16(d[nt], al + 4 * kt, bh + 2 * kt);
            #pragma unroll
            for (int kt = 0; kt < 4; kt++)
                mma_bf16(d[nt], ah + 4 * kt, bl + 2 * kt);
        }

        __syncthreads();   // everyone done READING A -> safe to overwrite

        // ---- epilogue: gates -> c,h update; write h back into A (hi/lo)
        #pragma unroll
        for (int nt = 0; nt < NTW; nt++) {
            // send what my xor-1 partner needs (its row's other gate pair)
            u64 send = half ? pack2f(d[nt][0], d[nt][1])
                            : pack2f(d[nt][2], d[nt][3]);
            u64 recv = __shfl_xor_sync(0xffffffffu, send, 1);
            float gi, gf, gg, go;
            if (half == 0) {   // holds (i,f) of row g
                gi = d[nt][0]; gf = d[nt][1];
                gg = lo_of(recv); go = hi_of(recv);
            } else {           // holds (g,o) of row g+8
                gg = d[nt][2]; go = d[nt][3];
                gi = lo_of(recv); gf = hi_of(recv);
            }
            float i_ = sigmoid_hw(gi);
            float f_ = sigmoid_hw(gf);
            float g_ = tanh_hw(gg);
            float o_ = sigmoid_hw(go);
            cst[nt] = fmaf(f_, cst[nt], i_ * g_);
            float hn = o_ * tanh_hw(cst[nt]);
            int cell = mycell[nt];
            if (cell < HDIM) {
                store_bf16_split(smem, SM_AH, SM_AL,
                                 (uint32_t)(myrow * 128 + cell * 2), hn);
                if (t == T_LEN - 1) partial = fmaf(wl[nt], hn, partial);
            }
        }
        // ---- x column for next step
        if (tid < MB && t + 1 < T_LEN) {
            store_bf16_split(smem, SM_AH, SM_AL,
                             (uint32_t)(tid * 128 + (HDIM + 1) * 2),
                             x_s[(t + 1) * MB + tid]);
        }
    }

    // ---- final linear: reduce 8 partials per row
    float* red = reinterpret_cast<float*>(smem + SM_RED);
    int slot = wn * 2 + (t3 >> 1);
    red[myrow * 8 + slot] = partial;
    __syncthreads();
    if (tid < MB) {
        float s = b_lin[0];
        #pragma unroll
        for (int i = 0; i < 8; i++) s += red[tid * 8 + i];
        out[b0 + tid] = s;
    }
}

extern "C" void kernel_launch(void* const* d_in, const int* in_sizes, int n_in,
                              void* d_out, int out_size) {
    const float* x     = (const float*)d_in[0];
    const float* W_ih  = (const float*)d_in[1];
    const float* W_hh  = (const float*)d_in[2];
    const float* b_ih  = (const float*)d_in[3];
    const float* b_hh  = (const float*)d_in[4];
    const float* W_lin = (const float*)d_in[5];
    const float* b_lin = (const float*)d_in[6];
    float* out = (float*)d_out;

    int Btot = in_sizes[0] / T_LEN;   // 8192

    static int smem_set = 0;
    if (!smem_set) {
        cudaFuncSetAttribute(lstm_mma_kernel,
                             cudaFuncAttributeMaxDynamicSharedMemorySize, SM_TOT);
        smem_set = 1;
    }
    lstm_mma_kernel<<<Btot / MB, NTHR, SM_TOT>>>(
        x, W_ih, W_hh, b_ih, b_hh, W_lin, b_lin, out);
}

// round 14
// speedup vs baseline: 2.7557x; 1.0914x over previous
#include <cuda_runtime.h>
#include <cuda_bf16.h>
#include <cstdint>

// LSTM_53815940218945 via mma.sync bf16x3 (Ootomo split), round 14:
//  - B_hi fragments RESIDENT in registers (56 regs, loaded once)
//  - per-n-tile fused GEMM+epilogue (d = 4 regs, reused)
//  - double-buffered A planes -> ONE barrier per step
// CTA = 64 batch rows, 512 threads = 16 warps (wm 0..3 x 16 rows, wn 0..3 x 7 n8-tiles).
// gates[64,224] = A[64,64] @ B[224,64]^T, passes AhiBhi + AloBhi + AhiBlo, f32 acc.
// A = [h | 1 | x_t | 0] bf16 hi/lo (SW128); B rows n = cell*4+gate.

#define T_LEN 256
#define HDIM  50
#define MB    64
#define NTHR  512
#define NTW   7
#define NROWS 224

// smem layout (bytes)
#define SM_XS   0                        // x_s[256][64] f32 = 65536
#define SM_A    65536                    // 2 planes x (hi 8192 + lo 8192) = 32768
#define SM_AHI(p) (SM_A + (p) * 16384)
#define SM_ALO(p) (SM_A + (p) * 16384 + 8192)
#define SM_BH   (SM_A + 32768)           // B_hi 224*128 = 28672
#define SM_BL   (SM_BH + 28672)          // B_lo 28672
#define SM_RED  (SM_BL + 28672)          // red[64][8] f32 = 2048
#define SM_TOT  (SM_RED + 2048)          // 157696

typedef unsigned long long u64;

__device__ __forceinline__ uint32_t smem_u32(const void* p) {
    uint32_t a;
    asm("{ .reg .u64 t; cvta.to.shared.u64 t, %1; cvt.u32.u64 %0, t; }"
        : "=r"(a) : "l"(p));
    return a;
}
__device__ __forceinline__ uint32_t sw128(uint32_t b) {
    return b ^ ((b >> 3) & 0x70);
}
__device__ __forceinline__ float tanh_hw(float x) {
    float y; asm("tanh.approx.f32 %0, %1;" : "=f"(y) : "f"(x)); return y;
}
__device__ __forceinline__ float sigmoid_hw(float x) {
    return fmaf(0.5f, tanh_hw(0.5f * x), 0.5f);
}
__device__ __forceinline__ u64 pack2f(float a, float b) {
    u64 r; asm("mov.b64 %0, {%1, %2};" : "=l"(r) : "f"(a), "f"(b)); return r;
}
__device__ __forceinline__ float lo_of(u64 v) { return __uint_as_float((unsigned)v); }
__device__ __forceinline__ float hi_of(u64 v) { return __uint_as_float((unsigned)(v >> 32)); }

#define LDSM4(r0, r1, r2, r3, a) \
    asm volatile("ldmatrix.sync.aligned.m8n8.x4.shared.b16 {%0,%1,%2,%3}, [%4];" \
                 : "=r"(r0), "=r"(r1), "=r"(r2), "=r"(r3) : "r"(a))

__device__ __forceinline__ void mma_bf16(float* d, const uint32_t* a,
                                         const uint32_t* b) {
    asm volatile(
        "mma.sync.aligned.m16n8k16.row.col.f32.bf16.bf16.f32 "
        "{%0,%1,%2,%3}, {%4,%5,%6,%7}, {%8,%9}, {%0,%1,%2,%3};"
        : "+f"(d[0]), "+f"(d[1]), "+f"(d[2]), "+f"(d[3])
        : "r"(a[0]), "r"(a[1]), "r"(a[2]), "r"(a[3]), "r"(b[0]), "r"(b[1]));
}

__device__ __forceinline__ void store_bf16_split(char* smem, uint32_t hi_base,
                                                 uint32_t lo_base,
                                                 uint32_t byte_off, float v) {
    __nv_bfloat16 hi = __float2bfloat16(v);
    float lo = v - __bfloat162float(hi);
    uint32_t so = sw128(byte_off);
    *reinterpret_cast<__nv_bfloat16*>(smem + hi_base + so) = hi;
    *reinterpret_cast<__nv_bfloat16*>(smem + lo_base + so) = __float2bfloat16(lo);
}

__global__ __launch_bounds__(NTHR, 1) void lstm_mma_kernel(
    const float* __restrict__ x,      // [B, T, 1]
    const float* __restrict__ W_ih,   // [200, 1]
    const float* __restrict__ W_hh,   // [200, 50]
    const float* __restrict__ b_ih,   // [200]
    const float* __restrict__ b_hh,   // [200]
    const float* __restrict__ W_lin,  // [1, 50]
    const float* __restrict__ b_lin,  // [1]
    float* __restrict__ out)          // [B]
{
    extern __shared__ __align__(1024) char smem[];
    const uint32_t sb = smem_u32(smem);
    const int tid  = threadIdx.x;
    const int wid  = tid >> 5, lane = tid & 31;
    const int wm   = wid & 3, wn = wid >> 2;
    const int m0   = wm * 16;
    const int nt0  = wn * NTW;
    const int b0   = blockIdx.x * MB;

    const int t3   = lane & 3;
    const int half = lane & 1;
    const int myrow = m0 + (lane >> 2) + 8 * half;

    float* x_s = reinterpret_cast<float*>(smem + SM_XS);

    // ---- load x tile (coalesced along t)
    for (int i = tid; i < MB * T_LEN; i += NTHR) {
        int r = i >> 8, t = i & (T_LEN - 1);
        x_s[t * MB + r] = x[(size_t)(b0 + r) * T_LEN + t];
    }
    // ---- zero both A planes (hi+lo)
    for (int i = tid; i < 32768 / 4; i += NTHR)
        reinterpret_cast<uint32_t*>(smem + SM_A)[i] = 0u;
    // ---- build static B tiles (hi/lo), rows n = cell*4 + gate, K-major SW128
    for (int idx = tid; idx < NROWS * 64; idx += NTHR) {
        int n = idx >> 6, k = idx & 63;
        float v = 0.0f;
        if (n < 200) {
            int cell = n >> 2, gate = n & 3;
            int wr = gate * HDIM + cell;            // gate order i,f,g,o
            if (k < HDIM)           v = W_hh[wr * HDIM + k];
            else if (k == HDIM)     v = b_ih[wr] + b_hh[wr];
            else if (k == HDIM + 1) v = W_ih[wr];
        }
        store_bf16_split(smem, SM_BH, SM_BL, (uint32_t)(n * 128 + k * 2), v);
    }
    __syncthreads();
    // ---- ones column (k=50, both planes) + x column (k=51) for t=0 (plane 0)
    if (tid < MB) {
        uint32_t so = sw128((uint32_t)(tid * 128 + HDIM * 2));
        *reinterpret_cast<__nv_bfloat16*>(smem + SM_AHI(0) + so) = __float2bfloat16(1.0f);
        *reinterpret_cast<__nv_bfloat16*>(smem + SM_AHI(1) + so) = __float2bfloat16(1.0f);
        store_bf16_split(smem, SM_AHI(0), SM_ALO(0),
                         (uint32_t)(tid * 128 + (HDIM + 1) * 2), x_s[tid]);
    }
    __syncthreads();   // B tiles complete before resident LDSM

    // ---- fragment addresses
    const uint32_t a_m    = (uint32_t)(m0 + (lane & 7) + 8 * ((lane >> 3) & 1));
    const uint32_t a_koff = (uint32_t)(8 * (lane >> 4));
    const uint32_t b_nrow = (uint32_t)(lane & 7);
    const uint32_t b_koff = (uint32_t)(8 * (lane >> 3));

    // ---- B_hi fragments RESIDENT (7 tiles x 8 regs)
    uint32_t bhr[NTW][8];
    #pragma unroll
    for (int nt = 0; nt < NTW; nt++) {
        uint32_t n = (uint32_t)((nt0 + nt) * 8) + b_nrow;
        uint32_t so0 = sw128(n * 128 + b_koff * 2);
        uint32_t so1 = sw128(n * 128 + (32 + b_koff) * 2);
        LDSM4(bhr[nt][0], bhr[nt][1], bhr[nt][2], bhr[nt][3], sb + SM_BH + so0);
        LDSM4(bhr[nt][4], bhr[nt][5], bhr[nt][6], bhr[nt][7], sb + SM_BH + so1);
    }

    float cst[NTW];
    #pragma unroll
    for (int nt = 0; nt < NTW; nt++) cst[nt] = 0.0f;
    float partial = 0.0f;

    #pragma unroll 1
    for (int t = 0; t < T_LEN; t++) {
        __syncthreads();   // plane p fully written (h from t-1, x col)
        const int p = t & 1;
        const uint32_t ahi = SM_AHI(p), alo = SM_ALO(p);
        const uint32_t nhi = SM_AHI(p ^ 1), nlo = SM_ALO(p ^ 1);

        // ---- A fragments: 4 k-tiles x (hi, lo)
        uint32_t ah[16], al[16];
        #pragma unroll
        for (int kt = 0; kt < 4; kt++) {
            uint32_t so = sw128(a_m * 128 + ((uint32_t)(kt * 16) + a_koff) * 2);
            LDSM4(ah[4*kt], ah[4*kt+1], ah[4*kt+2], ah[4*kt+3], sb + ahi + so);
            LDSM4(al[4*kt], al[4*kt+1], al[4*kt+2], al[4*kt+3], sb + alo + so);
        }

        // ---- per n-tile: B_lo load + 12 MMA + fused epilogue
        #pragma unroll
        for (int nt = 0; nt < NTW; nt++) {
            uint32_t n = (uint32_t)((nt0 + nt) * 8) + b_nrow;
            uint32_t bl[8];
            {
                uint32_t so0 = sw128(n * 128 + b_koff * 2);
                uint32_t so1 = sw128(n * 128 + (32 + b_koff) * 2);
                LDSM4(bl[0], bl[1], bl[2], bl[3], sb + SM_BL + so0);
                LDSM4(bl[4], bl[5], bl[6], bl[7], sb + SM_BL + so1);
            }
            float d[4] = {0.0f, 0.0f, 0.0f, 0.0f};
            #pragma unroll
            for (int kt = 0; kt < 4; kt++)
                mma_bf16(d, ah + 4 * kt, bhr[nt] + 2 * kt);
            #pragma unroll
            for (int kt = 0; kt < 4; kt++)
                mma_bf16(d, al + 4 * kt, bhr[nt] + 2 * kt);
            #pragma unroll
            for (int kt = 0; kt < 4; kt++)
                mma_bf16(d, ah + 4 * kt, bl + 2 * kt);

            // ---- epilogue for this tile
            u64 send = half ? pack2f(d[0], d[1]) : pack2f(d[2], d[3]);
            u64 recv = __shfl_xor_sync(0xffffffffu, send, 1);
            float gi, gf, gg, go;
            if (half == 0) {
                gi = d[0]; gf = d[1]; gg = lo_of(recv); go = hi_of(recv);
            } else {
                gg = d[2]; go = d[3]; gi = lo_of(recv); gf = hi_of(recv);
            }
            float i_ = sigmoid_hw(gi);
            float f_ = sigmoid_hw(gf);
            float g_ = tanh_hw(gg);
            float o_ = sigmoid_hw(go);
            cst[nt] = fmaf(f_, cst[nt], i_ * g_);
            float hn = o_ * tanh_hw(cst[nt]);
            int cell = (nt0 + nt) * 2 + (t3 >> 1);
            if (cell < HDIM) {
                store_bf16_split(smem, nhi, nlo,
                                 (uint32_t)(myrow * 128 + cell * 2), hn);
                if (t == T_LEN - 1)
                    partial = fmaf(__ldg(&W_lin[cell]), hn, partial);
            }
        }
        // ---- x column for next step into next plane
        if (tid < MB && t + 1 < T_LEN) {
            store_bf16_split(smem, nhi, nlo,
                             (uint32_t)(tid * 128 + (HDIM + 1) * 2),
                             x_s[(t + 1) * MB + tid]);
        }
    }

    // ---- final linear: reduce 8 partials per row
    float* red = reinterpret_cast<float*>(smem + SM_RED);
    int slot = wn * 2 + (t3 >> 1);
    red[myrow * 8 + slot] = partial;
    __syncthreads();
    if (tid < MB) {
        float s = b_lin[0];
        #pragma unroll
        for (int i = 0; i < 8; i++) s += red[tid * 8 + i];
        out[b0 + tid] = s;
    }
}

extern "C" void kernel_launch(void* const* d_in, const int* in_sizes, int n_in,
                              void* d_out, int out_size) {
    const float* x     = (const float*)d_in[0];
    const float* W_ih  = (const float*)d_in[1];
    const float* W_hh  = (const float*)d_in[2];
    const float* b_ih  = (const float*)d_in[3];
    const float* b_hh  = (const float*)d_in[4];
    const float* W_lin = (const float*)d_in[5];
    const float* b_lin = (const float*)d_in[6];
    float* out = (float*)d_out;

    int Btot = in_sizes[0] / T_LEN;   // 8192

    static int smem_set = 0;
    if (!smem_set) {
        cudaFuncSetAttribute(lstm_mma_kernel,
                             cudaFuncAttributeMaxDynamicSharedMemorySize, SM_TOT);
        smem_set = 1;
    }
    lstm_mma_kernel<<<Btot / MB, NTHR, SM_TOT>>>(
        x, W_ih, W_hh, b_ih, b_hh, W_lin, b_lin, out);
}